// round 15
// baseline (speedup 1.0000x reference)
#include <cuda_runtime.h>

typedef unsigned long long ull;

#define T_LEN 512
#define NB    32            // batch rows per CTA
#define NTH   512           // 32 chunks (8 gate cols) x 16 row-pairs
#define GC    256           // padded gate cols: col = 4*u + g, u < 64 (real u < 50)

// ---- shared memory layout (float offsets) ----
#define OFF_WT1  0                       // [100][256]: k<50 Wih1^T, k>=50 Whh1^T (prescaled)
#define OFF_WT0  (OFF_WT1 + 100*GC)     // [50][256]: Whh0^T (prescaled)
#define OFF_WX0  (OFF_WT0 + 50*GC)      // [256] Wih0 column (prescaled)
#define OFF_B0   (OFF_WX0 + GC)
#define OFF_B1   (OFF_B0  + GC)
#define OFF_HSP0 (OFF_B1  + GC)         // [50][32] ull (h,h) pairs = 3200 floats
#define OFF_HSP1 (OFF_HSP0 + 3200)
#define OFF_FC   (OFF_HSP1 + 3200)
#define SMEMF    (OFF_FC + 64)          // 45632 floats = 182528 B

#define SCALE_S (-1.4426950408889634f)  // sigmoid gates: sig(x)=rcp(1+ex2(x*-log2e))
#define SCALE_T (-2.8853900817779268f)  // tanh: tanh(x)=2*rcp(1+ex2(x*-2log2e))-1

// ---- packed f32x2 + MUFU helpers ----
__device__ __forceinline__ ull pack2(float x, float y) {
    ull r; asm("mov.b64 %0, {%1, %2};" : "=l"(r) : "f"(x), "f"(y)); return r;
}
__device__ __forceinline__ void unpack2(ull v, float& x, float& y) {
    asm("mov.b64 {%0, %1}, %2;" : "=f"(x), "=f"(y) : "l"(v));
}
__device__ __forceinline__ void fma2(ull& d, ull a, ull b) {
    asm("fma.rn.f32x2 %0, %1, %2, %0;" : "+l"(d) : "l"(a), "l"(b));
}
__device__ __forceinline__ float fex2(float x) {
    float r; asm("ex2.approx.f32 %0, %1;" : "=f"(r) : "f"(x)); return r;
}
__device__ __forceinline__ float frcp(float x) {
    float r; asm("rcp.approx.f32 %0, %1;" : "=f"(r) : "f"(x)); return r;
}

// acc layout: a[0..3] = row0 (4 f32x2 = 8 cols), a[4..7] = row1
// 8 cols x 2 rows += (ha,hb) * w[8]; weights 32B = 2 x LDS.128 (2-way/warp, 32B/wavefront)
__device__ __forceinline__ void mvk4(ull* a, ull ha, ull hb, const float* w) {
    const ulonglong2* w2 = reinterpret_cast<const ulonglong2*>(w);
    ulonglong2 v0 = w2[0], v1 = w2[1];
    fma2(a[0], ha, v0.x);  fma2(a[1], ha, v0.y);
    fma2(a[2], ha, v1.x);  fma2(a[3], ha, v1.y);
    fma2(a[4], hb, v0.x);  fma2(a[5], hb, v0.y);
    fma2(a[6], hb, v1.x);  fma2(a[7], hb, v1.y);
}
__device__ __forceinline__ void initb4(ull* a, const float* b) {
    const ulonglong2* b2 = reinterpret_cast<const ulonglong2*>(b);
    ulonglong2 v0 = b2[0], v1 = b2[1];
    a[0] = v0.x; a[1] = v0.y; a[2] = v1.x; a[3] = v1.y;
    a[4] = v0.x; a[5] = v0.y; a[6] = v1.x; a[7] = v1.y;
}
// load pre-splatted h pairs for rows rp2, rp2+1: one LDS.128, zero MOVs
__device__ __forceinline__ void hload(const ull* hs, int idx, ull& ha, ull& hb) {
    ulonglong2 v = *reinterpret_cast<const ulonglong2*>(hs + idx);
    ha = v.x; hb = v.y;
}

// unit J (0..1) LSTM cell update for BOTH rows; gates prescaled
// (i/f/o by -log2e, g by -2log2e); writes both (h,h) pairs as STS.128
template<int J>
__device__ __forceinline__ void act_u2(const ull* a, float* cs, ull* hs, int u0, int rp2) {
    float gi0, gf0, gg0, go0, gi1, gf1, gg1, go1;
    unpack2(a[2*J],         gi0, gf0);
    unpack2(a[2*J + 1],     gg0, go0);
    unpack2(a[4 + 2*J],     gi1, gf1);
    unpack2(a[4 + 2*J + 1], gg1, go1);
    float si0 = frcp(1.f + fex2(gi0)), sf0 = frcp(1.f + fex2(gf0));
    float sg0 = frcp(1.f + fex2(gg0)), so0 = frcp(1.f + fex2(go0));
    float si1 = frcp(1.f + fex2(gi1)), sf1 = frcp(1.f + fex2(gf1));
    float sg1 = frcp(1.f + fex2(gg1)), so1 = frcp(1.f + fex2(go1));
    float tg0 = fmaf(2.f, sg0, -1.f),  tg1 = fmaf(2.f, sg1, -1.f);
    float cn0 = fmaf(sf0, cs[2*J],     si0 * tg0);
    float cn1 = fmaf(sf1, cs[2*J + 1], si1 * tg1);
    cs[2*J] = cn0; cs[2*J + 1] = cn1;
    float h0v = so0 * fmaf(2.f, frcp(1.f + fex2(SCALE_T * cn0)), -1.f);
    float h1v = so1 * fmaf(2.f, frcp(1.f + fex2(SCALE_T * cn1)), -1.f);
    if (u0 + J < 50) {
        ulonglong2 st;
        st.x = pack2(h0v, h0v);
        st.y = pack2(h1v, h1v);
        *reinterpret_cast<ulonglong2*>(hs + (u0 + J)*32 + rp2) = st;   // STS.128
    }
}

__global__ void __launch_bounds__(NTH, 1)
lstm_v5_kernel(const float* __restrict__ x,
               const float* __restrict__ Wih0, const float* __restrict__ Whh0,
               const float* __restrict__ bih0, const float* __restrict__ bhh0,
               const float* __restrict__ Wih1, const float* __restrict__ Whh1,
               const float* __restrict__ bih1, const float* __restrict__ bhh1,
               const float* __restrict__ fcw_g, const float* __restrict__ fcb_g,
               float* __restrict__ out)
{
    extern __shared__ float sm[];
    float* wt1 = sm + OFF_WT1;
    float* wt0 = sm + OFF_WT0;
    float* wx0 = sm + OFF_WX0;
    float* bs0 = sm + OFF_B0;
    float* bs1 = sm + OFF_B1;
    ull*   hs0 = reinterpret_cast<ull*>(sm + OFF_HSP0);   // [u][r] = (h,h)
    ull*   hs1 = reinterpret_cast<ull*>(sm + OFF_HSP1);
    float* fcs = sm + OFF_FC;

    const int tid = threadIdx.x;
    const int b0  = blockIdx.x * NB;

    // ---------------- staging (prescaled, transposed, padded) ----------------
    for (int idx = tid; idx < 100*GC; idx += NTH) {
        int k = idx >> 8, col = idx & 255;
        int u = col >> 2, g = col & 3;
        float s = (g == 2) ? SCALE_T : SCALE_S;
        float v = 0.f;
        if (u < 50) {
            int row = g*50 + u;
            v = (k < 50) ? Wih1[row*50 + k] : Whh1[row*50 + (k - 50)];
        }
        wt1[idx] = v * s;
    }
    for (int idx = tid; idx < 50*GC; idx += NTH) {
        int k = idx >> 8, col = idx & 255;
        int u = col >> 2, g = col & 3;
        float s = (g == 2) ? SCALE_T : SCALE_S;
        wt0[idx] = (u < 50) ? Whh0[(g*50 + u)*50 + k] * s : 0.f;
    }
    if (tid < GC) {
        int u = tid >> 2, g = tid & 3;
        float s = (g == 2) ? SCALE_T : SCALE_S;
        int row = g*50 + u;
        wx0[tid] = (u < 50) ? Wih0[row] * s : 0.f;
        bs0[tid] = (u < 50) ? (bih0[row] + bhh0[row]) * s : 0.f;
        bs1[tid] = (u < 50) ? (bih1[row] + bhh1[row]) * s : 0.f;
    }
    if (tid < 50) fcs[tid] = fcw_g[tid];
    for (int idx = tid; idx < 1600; idx += NTH) { hs0[idx] = 0ull; hs1[idx] = 0ull; }
    __syncthreads();

    // ---------------- per-thread geometry ----------------
    const int rph = tid & 15;            // row-pair 0..15 (rows 2rph, 2rph+1)
    const int c   = tid >> 4;            // chunk 0..31 (8 gate cols = 2 units)
    const int rp2 = 2 * rph;
    const int co  = 8 * c;               // column offset
    const int u0  = 2 * c;               // first unit (>=50 -> pure padding)

    const float* wt1c = wt1 + co;
    const float* wt0c = wt0 + co;
    const float* wx0c = wx0 + co;
    const float* b0c  = bs0 + co;
    const float* b1c  = bs1 + co;
    const float* xrow = x + (size_t)(b0 + rp2) * T_LEN;   // row rp2; +T_LEN for rp2+1

    float c0s[4], c1s[4];                // c-state [unit J][row]
    #pragma unroll
    for (int j = 0; j < 4; ++j) { c0s[j] = 0.f; c1s[j] = 0.f; }

    ull g1[8];                           // saved L1 gate sums from previous t
    float xv0, xv1;                      // x(t+1) for rows rp2, rp2+1

    // ---------------- prologue: h0(0) from x(0) + bias ----------------
    {
        ull acc[8];
        initb4(acc, b0c);
        float p0 = xrow[0], p1 = xrow[T_LEN];
        mvk4(acc, pack2(p0, p0), pack2(p1, p1), wx0c);
        act_u2<0>(acc, c0s, hs0, u0, rp2);
        act_u2<1>(acc, c0s, hs0, u0, rp2);
        xv0 = xrow[1]; xv1 = xrow[T_LEN + 1];
    }
    __syncthreads();

    // ---------------- main loop ----------------
    // body(t): h0(t)-matvec -> acc1 (L1(t)) + acc0 (L0(t+1)); act1(t-1) interleaved.
    //          BAR. h1(t-1)-matvec finishes acc1; act0 -> h0(t+1) interleaved. BAR.
    for (int t = 0; t < T_LEN; ++t) {
        ull acc0[8], acc1[8];
        initb4(acc1, b1c);
        initb4(acc0, b0c);
        mvk4(acc0, pack2(xv0, xv0), pack2(xv1, xv1), wx0c);   // x(t+1) rank-1
        int tn = (t + 2 < T_LEN) ? t + 2 : T_LEN - 1;
        float xn0 = xrow[tn], xn1 = xrow[T_LEN + tn];          // prefetch x(t+2)

        // -- h0(t) phase: 2 sub-ranges, act1(t-1) slices interleaved --
        #pragma unroll 5
        for (int k = 0; k < 25; ++k) {
            ull ha, hb; hload(hs0, k*32 + rp2, ha, hb);        // LDS.128, pre-splatted
            mvk4(acc1, ha, hb, wt1c + k*GC);
            mvk4(acc0, ha, hb, wt0c + k*GC);
        }
        if (t > 0) act_u2<0>(g1, c1s, hs1, u0, rp2);
        #pragma unroll 5
        for (int k = 25; k < 50; ++k) {
            ull ha, hb; hload(hs0, k*32 + rp2, ha, hb);
            mvk4(acc1, ha, hb, wt1c + k*GC);
            mvk4(acc0, ha, hb, wt0c + k*GC);
        }
        if (t > 0) act_u2<1>(g1, c1s, hs1, u0, rp2);

        __syncthreads();   // h1(t-1) stores visible; h0(t) reads done before h0(t+1) writes

        // -- h1(t-1) phase: finish acc1; act0 -> h0(t+1) interleaved --
        #pragma unroll 5
        for (int k = 0; k < 25; ++k) {
            ull ha, hb; hload(hs1, k*32 + rp2, ha, hb);
            mvk4(acc1, ha, hb, wt1c + (50 + k)*GC);
        }
        act_u2<0>(acc0, c0s, hs0, u0, rp2);
        #pragma unroll 5
        for (int k = 25; k < 50; ++k) {
            ull ha, hb; hload(hs1, k*32 + rp2, ha, hb);
            mvk4(acc1, ha, hb, wt1c + (50 + k)*GC);
        }
        act_u2<1>(acc0, c0s, hs0, u0, rp2);

        #pragma unroll
        for (int i = 0; i < 8; ++i) g1[i] = acc1[i];   // defer act1 to next body
        xv0 = xn0; xv1 = xn1;

        __syncthreads();   // h0(t+1) stores visible before next h0-phase reads
    }

    // ---------------- epilogue: act1(511) then FC ----------------
    act_u2<0>(g1, c1s, hs1, u0, rp2);
    act_u2<1>(g1, c1s, hs1, u0, rp2);
    __syncthreads();

    if (tid < NB) {
        float s = fcb_g[0];
        const float* h1f = sm + OFF_HSP1;     // low float of each (h,h) pair
        #pragma unroll
        for (int u = 0; u < 50; ++u)
            s += fcs[u] * h1f[(u*32 + tid) * 2];
        out[b0 + tid] = s;
    }
}

extern "C" void kernel_launch(void* const* d_in, const int* in_sizes, int n_in,
                              void* d_out, int out_size)
{
    const float* x    = (const float*)d_in[0];
    const float* Wih0 = (const float*)d_in[1];
    const float* Whh0 = (const float*)d_in[2];
    const float* bih0 = (const float*)d_in[3];
    const float* bhh0 = (const float*)d_in[4];
    const float* Wih1 = (const float*)d_in[5];
    const float* Whh1 = (const float*)d_in[6];
    const float* bih1 = (const float*)d_in[7];
    const float* bhh1 = (const float*)d_in[8];
    const float* fcw  = (const float*)d_in[9];
    const float* fcb  = (const float*)d_in[10];
    float* out = (float*)d_out;

    const int B = in_sizes[0] / T_LEN;            // 4096
    const int grid = B / NB;                      // 128 CTAs
    const size_t smem = SMEMF * sizeof(float);    // 182528 B

    cudaFuncSetAttribute(lstm_v5_kernel,
                         cudaFuncAttributeMaxDynamicSharedMemorySize, (int)smem);

    lstm_v5_kernel<<<grid, NTH, smem>>>(
        x, Wih0, Whh0, bih0, bhh0, Wih1, Whh1, bih1, bhh1, fcw, fcb, out);
}